// round 6
// baseline (speedup 1.0000x reference)
#include <cuda_runtime.h>

#define FM_H 120
#define FM_W 120
#define FM_C 64
#define FM_HW (FM_H * FM_W)
#define N_BOX 4096

// ---------------- device scratch (no allocations allowed) ----------------
__device__ float g_fmT[FM_HW * FM_C];          // [H*W][C]  3.69 MB
__device__ float g_pooled[N_BOX * 3 * 64];     // [n][scale3|scale7|scale11] == concat[n][192]
__device__ float g_gvec[64];                   // global avg pool
__device__ __align__(16) float g_pb1eff[128];  // pb1 + gh @ p1[192:256]

// ---------------- helpers ----------------
__device__ __forceinline__ float4 relu4(float4 v) {
    v.x = fmaxf(v.x, 0.f); v.y = fmaxf(v.y, 0.f);
    v.z = fmaxf(v.z, 0.f); v.w = fmaxf(v.w, 0.f);
    return v;
}

__device__ __forceinline__ float4 half_reduce(float4 a) {
    a.x += __shfl_down_sync(0xffffffffu, a.x, 16);
    a.y += __shfl_down_sync(0xffffffffu, a.y, 16);
    a.z += __shfl_down_sync(0xffffffffu, a.z, 16);
    a.w += __shfl_down_sync(0xffffffffu, a.w, 16);
    return a;
}

// ---------------- kernel 1: transpose [C,H,W]->[H*W,C]  +  global mean ----------------
__global__ void k_prep(const float* __restrict__ fm) {
    if (blockIdx.x < FM_HW / 64) {
        __shared__ float tile[64 * 65];
        const int p0 = blockIdx.x * 64;
        const int t = threadIdx.x;
#pragma unroll
        for (int i = 0; i < 16; i++) {
            int idx = i * 256 + t;
            int c = idx >> 6, p = idx & 63;
            tile[p * 65 + c] = fm[c * FM_HW + p0 + p];
        }
        __syncthreads();
#pragma unroll
        for (int i = 0; i < 16; i++) {
            int idx = i * 256 + t;
            int p = idx >> 6, c = idx & 63;
            g_fmT[(p0 + p) * 64 + c] = tile[p * 65 + c];
        }
    } else {
        __shared__ float red[256];
        const int c = blockIdx.x - FM_HW / 64;
        float s = 0.f;
        for (int p = threadIdx.x; p < FM_HW; p += 256) s += fm[c * FM_HW + p];
        red[threadIdx.x] = s;
        __syncthreads();
        for (int st = 128; st > 0; st >>= 1) {
            if (threadIdx.x < st) red[threadIdx.x] += red[threadIdx.x + st];
            __syncthreads();
        }
        if (threadIdx.x == 0) g_gvec[c] = red[0] * (1.0f / (float)FM_HW);
    }
}

// ---------------- kernel 2: shared head on g, fold into pb1eff ----------------
__global__ void k_headg(const float* __restrict__ w1, const float* __restrict__ b1,
                        const float* __restrict__ w2, const float* __restrict__ b2,
                        const float* __restrict__ p1, const float* __restrict__ pb1) {
    __shared__ float h1[128];
    __shared__ float gh[64];
    const int t = threadIdx.x;  // 128 threads
    {
        float acc = b1[t];
#pragma unroll 8
        for (int c = 0; c < 64; c++) acc += g_gvec[c] * w1[c * 128 + t];
        h1[t] = fmaxf(acc, 0.f);
    }
    __syncthreads();
    if (t < 64) {
        float acc = b2[t];
#pragma unroll 8
        for (int k = 0; k < 128; k++) acc += h1[k] * w2[k * 64 + t];
        gh[t] = fmaxf(acc, 0.f);
    }
    __syncthreads();
    {
        float acc = pb1[t];
#pragma unroll 8
        for (int j = 0; j < 64; j++) acc += gh[j] * p1[(192 + j) * 128 + t];
        g_pb1eff[t] = acc;
    }
}

// ---------------- kernel 3: ROI pooling (unchanged) ----------------
template <int R>
__device__ __forceinline__ float4 accum_scale(const float4* __restrict__ base4,
                                              float Ax, float Sx, float Ay, float Sy,
                                              int j0, int j1, int half, int lane4) {
    const float invR = 1.0f / (float)R;
    float4 acc = make_float4(0.f, 0.f, 0.f, 0.f);
    const int steps = ((j1 - j0) + 1) >> 1;
#pragma unroll 4
    for (int i = 0; i < steps; i++) {
        int j = j0 + 2 * i + half;
        float valid = (j < j1) ? 1.f : 0.f;
        int jc = min(j, j1 - 1);
        int row = jc / R;
        int col = jc - row * R;
        float iy = Ay + Sy * ((2.0f * row + 1.0f) * invR - 1.0f);
        float ix = Ax + Sx * ((2.0f * col + 1.0f) * invR - 1.0f);
        float y0f = floorf(iy), x0f = floorf(ix);
        float wy = iy - y0f, wx = ix - x0f;
        int y0 = (int)y0f, x0 = (int)x0f;
        float vy0 = (y0 >= 0 && y0 < FM_H) ? 1.f : 0.f;
        float vy1 = (y0 >= -1 && y0 < FM_H - 1) ? 1.f : 0.f;
        float vx0 = (x0 >= 0 && x0 < FM_W) ? 1.f : 0.f;
        float vx1 = (x0 >= -1 && x0 < FM_W - 1) ? 1.f : 0.f;
        int y0c = min(max(y0, 0), FM_H - 1);
        int y1c = min(max(y0 + 1, 0), FM_H - 1);
        int x0c = min(max(x0, 0), FM_W - 1);
        int x1c = min(max(x0 + 1, 0), FM_W - 1);
        float wy0 = (1.f - wy) * vy0 * valid;
        float wy1 = wy * vy1 * valid;
        float w00 = (1.f - wx) * vx0 * wy0;
        float w10 = wx * vx1 * wy0;
        float w01 = (1.f - wx) * vx0 * wy1;
        float w11 = wx * vx1 * wy1;
        const float4* r0 = base4 + y0c * (FM_W * 16) + lane4;
        const float4* r1 = base4 + y1c * (FM_W * 16) + lane4;
        float4 v00 = __ldg(r0 + x0c * 16);
        float4 v10 = __ldg(r0 + x1c * 16);
        float4 v01 = __ldg(r1 + x0c * 16);
        float4 v11 = __ldg(r1 + x1c * 16);
        acc.x += w00 * v00.x + w10 * v10.x + w01 * v01.x + w11 * v11.x;
        acc.y += w00 * v00.y + w10 * v10.y + w01 * v01.y + w11 * v11.y;
        acc.z += w00 * v00.z + w10 * v10.z + w01 * v01.z + w11 * v11.z;
        acc.w += w00 * v00.w + w10 * v10.w + w01 * v01.w + w11 * v11.w;
    }
    return acc;
}

__global__ void __launch_bounds__(256) k_pool(const float* __restrict__ boxes) {
    __shared__ float4 s11[4][16];
    const int w = threadIdx.x >> 5;
    const int lane = threadIdx.x & 31;
    const int boxL = w >> 1;
    const int role = w & 1;
    const int half = lane >> 4;
    const int lane4 = lane & 15;
    const int box = blockIdx.x * 4 + boxL;

    const float4 b = __ldg(reinterpret_cast<const float4*>(boxes) + box);
    const float sc = 2.0f / 960.0f;
    float x1 = b.x * sc - 1.f, y1 = b.y * sc - 1.f;
    float x2 = b.z * sc - 1.f, y2 = b.w * sc - 1.f;
    float cx = 0.5f * (x1 + x2), cy = 0.5f * (y1 + y2);
    float bw = fmaxf(x2 - x1, 1e-6f), bh = fmaxf(y2 - y1, 1e-6f);
    float Ax = 0.5f * ((cx + 1.f) * (float)FM_W - 1.f);
    float Ay = 0.5f * ((cy + 1.f) * (float)FM_H - 1.f);
    float Sx = bw * (0.25f * (float)FM_W);
    float Sy = bh * (0.25f * (float)FM_H);

    const float4* base4 = reinterpret_cast<const float4*>(g_fmT);
    float4 a11;

    if (role == 0) {
        float4 a7 = accum_scale<7>(base4, Ax, Sx, Ay, Sy, 0, 49, half, lane4);
        a11 = accum_scale<11>(base4, Ax, Sx, Ay, Sy, 0, 44, half, lane4);
        a7 = half_reduce(a7);
        a11 = half_reduce(a11);
        if (lane < 16) {
            s11[boxL][lane4] = a11;
            const float s7 = (1.0f / 7.0f) * (1.0f / 7.0f);
            float4 o = make_float4(a7.x * s7, a7.y * s7, a7.z * s7, a7.w * s7);
            reinterpret_cast<float4*>(g_pooled + box * 192 + 64)[lane4] = o;
        }
    } else {
        float4 a3 = accum_scale<3>(base4, Ax, Sx, Ay, Sy, 0, 9, half, lane4);
        a11 = accum_scale<11>(base4, Ax, Sx, Ay, Sy, 44, 121, half, lane4);
        a3 = half_reduce(a3);
        a11 = half_reduce(a11);
        if (lane < 16) {
            const float s3 = (1.0f / 3.0f) * (1.0f / 3.0f);
            float4 o = make_float4(a3.x * s3, a3.y * s3, a3.z * s3, a3.w * s3);
            reinterpret_cast<float4*>(g_pooled + box * 192)[lane4] = o;
        }
    }
    __syncthreads();
    if (role == 1 && lane < 16) {
        float4 p = s11[boxL][lane4];
        const float s11c = (1.0f / 11.0f) * (1.0f / 11.0f);
        float4 o = make_float4((p.x + a11.x) * s11c, (p.y + a11.y) * s11c,
                               (p.z + a11.z) * s11c, (p.w + a11.w) * s11c);
        reinterpret_cast<float4*>(g_pooled + box * 192 + 128)[lane4] = o;
    }
}

// ---------------- kernel 4: fused MLP — 8 boxes/block, grid 512 ----------------
// sA: X[24][64] then concat[8][192]  (1536 floats)
// sB: H[24][128] then h2[8][128]     (3072 floats)
__global__ void __launch_bounds__(256) k_mlp(const float* __restrict__ w1, const float* __restrict__ b1,
                                             const float* __restrict__ w2, const float* __restrict__ b2,
                                             const float* __restrict__ p1, const float* __restrict__ p2,
                                             const float* __restrict__ pb2, float* __restrict__ out) {
    __shared__ float sA[24 * 64];
    __shared__ float sB[24 * 128];
    const int t = threadIdx.x;
    const int wg = t >> 5;   // 8 warps
    const int cg = t & 31;   // lane

    // phase 0: load pooled rows [24][64] = [8 boxes][192]
    {
        const float4* s4 = reinterpret_cast<const float4*>(g_pooled + blockIdx.x * (8 * 192));
        float4* d4 = reinterpret_cast<float4*>(sA);
        d4[t] = __ldg(s4 + t);
        if (t < 128) d4[256 + t] = __ldg(s4 + 256 + t);
    }
    __syncthreads();

    // phase 1: H[24][128] = relu(X @ w1 + b1); warp wg -> rows 3wg..3wg+2, lane -> cols 4cg..4cg+3
    {
        float4 acc[3];
        float4 bv = __ldg(reinterpret_cast<const float4*>(b1) + cg);
#pragma unroll
        for (int rr = 0; rr < 3; rr++) acc[rr] = bv;
        const float4* w1r = reinterpret_cast<const float4*>(w1) + cg;
#pragma unroll 8
        for (int c = 0; c < 64; c++) {
            float4 wv = __ldg(w1r + c * 32);
#pragma unroll
            for (int rr = 0; rr < 3; rr++) {
                float x = sA[(wg * 3 + rr) * 64 + c];   // warp broadcast
                acc[rr].x += x * wv.x; acc[rr].y += x * wv.y;
                acc[rr].z += x * wv.z; acc[rr].w += x * wv.w;
            }
        }
#pragma unroll
        for (int rr = 0; rr < 3; rr++)
            reinterpret_cast<float4*>(sB + (wg * 3 + rr) * 128)[cg] = relu4(acc[rr]);
    }
    __syncthreads();

    // phase 2: feats[24][64] = relu(H @ w2 + b2) -> sA as concat[8][192]
    // warp wg -> box wg (rows 3wg..3wg+2), lane -> cols 2cg..2cg+1
    {
        float2 acc[3];
        float2 bv = __ldg(reinterpret_cast<const float2*>(b2) + cg);
#pragma unroll
        for (int rr = 0; rr < 3; rr++) acc[rr] = bv;
        const float2* w2r = reinterpret_cast<const float2*>(w2) + cg;
#pragma unroll 8
        for (int k = 0; k < 128; k++) {
            float2 wv = __ldg(w2r + k * 32);
#pragma unroll
            for (int rr = 0; rr < 3; rr++) {
                float h = sB[(wg * 3 + rr) * 128 + k];  // warp broadcast
                acc[rr].x += h * wv.x; acc[rr].y += h * wv.y;
            }
        }
#pragma unroll
        for (int rr = 0; rr < 3; rr++) {
            float2 o = make_float2(fmaxf(acc[rr].x, 0.f), fmaxf(acc[rr].y, 0.f));
            reinterpret_cast<float2*>(sA + wg * 192 + rr * 64)[cg] = o;
        }
    }
    __syncthreads();

    // phase 3: h2[8][128] = relu(concat @ p1[0:192] + pb1eff) -> sB
    // warp wg -> box wg, lane -> cols 4cg..4cg+3
    {
        float4 acc = __ldg(reinterpret_cast<const float4*>(g_pb1eff) + cg);
        const float4* p1r = reinterpret_cast<const float4*>(p1) + cg;
#pragma unroll 8
        for (int j = 0; j < 192; j++) {
            float4 wv = __ldg(p1r + j * 32);
            float x = sA[wg * 192 + j];                 // warp broadcast
            acc.x += x * wv.x; acc.y += x * wv.y;
            acc.z += x * wv.z; acc.w += x * wv.w;
        }
        reinterpret_cast<float4*>(sB + wg * 128)[cg] = relu4(acc);
    }
    __syncthreads();

    // phase 4: out[8][64] = relu(h2 @ p2 + pb2); warp wg -> box wg, lane -> cols 2cg..2cg+1
    {
        float2 acc = __ldg(reinterpret_cast<const float2*>(pb2) + cg);
        const float2* p2r = reinterpret_cast<const float2*>(p2) + cg;
#pragma unroll 8
        for (int k = 0; k < 128; k++) {
            float2 wv = __ldg(p2r + k * 32);
            float h = sB[wg * 128 + k];                 // warp broadcast
            acc.x += h * wv.x; acc.y += h * wv.y;
        }
        float2 o = make_float2(fmaxf(acc.x, 0.f), fmaxf(acc.y, 0.f));
        reinterpret_cast<float2*>(out + (blockIdx.x * 8 + wg) * 64)[cg] = o;
    }
}

// ---------------- launch ----------------
extern "C" void kernel_launch(void* const* d_in, const int* in_sizes, int n_in,
                              void* d_out, int out_size) {
    const float* fm    = (const float*)d_in[0];
    const float* boxes = (const float*)d_in[1];
    const float* w1    = (const float*)d_in[2];
    const float* b1    = (const float*)d_in[3];
    const float* w2    = (const float*)d_in[4];
    const float* b2    = (const float*)d_in[5];
    const float* p1    = (const float*)d_in[6];
    const float* pb1   = (const float*)d_in[7];
    const float* p2    = (const float*)d_in[8];
    const float* pb2   = (const float*)d_in[9];
    float* out = (float*)d_out;

    k_prep<<<FM_HW / 64 + 64, 256>>>(fm);
    k_headg<<<1, 128>>>(w1, b1, w2, b2, p1, pb1);
    k_pool<<<N_BOX / 4, 256>>>(boxes);
    k_mlp<<<N_BOX / 8, 256>>>(w1, b1, w2, b2, p1, p2, pb2, out);
}